// round 16
// baseline (speedup 1.0000x reference)
#include <cuda_runtime.h>
#include <cstdint>

// Problem shape (fixed by the dataset)
#define B_ROWS    16384
#define D_DIM     2048
#define D4        512                 // float4 per row (8 KB)
#define ROW_BYTES 8192
#define NBLK      592                 // 148 SMs x 4 CTAs, persistent, one wave
#define NTHR      256
#define STAGES    4                   // R11's proven ring: 4 x 8 KB
#define WARPS_PER_BLK (NTHR / 32)

__device__ float g_partials[NBLK];
__device__ unsigned int g_count;      // zero-init at load; reset by last block

__device__ __forceinline__ uint32_t smem_u32(const void* p) {
    return (uint32_t)__cvta_generic_to_shared(p);
}
__device__ __forceinline__ void mbar_init(uint32_t mbar, uint32_t cnt) {
    asm volatile("mbarrier.init.shared.b64 [%0], %1;" :: "r"(mbar), "r"(cnt) : "memory");
}
__device__ __forceinline__ void mbar_expect_tx(uint32_t mbar, uint32_t bytes) {
    asm volatile("mbarrier.arrive.expect_tx.shared.b64 _, [%0], %1;"
                 :: "r"(mbar), "r"(bytes) : "memory");
}
__device__ __forceinline__ void bulk_g2s(uint32_t dst, const void* src,
                                         uint32_t bytes, uint32_t mbar) {
    asm volatile(
        "cp.async.bulk.shared::cluster.global.mbarrier::complete_tx::bytes "
        "[%0], [%1], %2, [%3];"
        :: "r"(dst), "l"(src), "r"(bytes), "r"(mbar) : "memory");
}
__device__ __forceinline__ void mbar_wait(uint32_t mbar, uint32_t parity) {
    asm volatile(
        "{\n\t"
        ".reg .pred P;\n\t"
        "W%=:\n\t"
        "mbarrier.try_wait.parity.acquire.cta.shared::cta.b64 P, [%0], %1, 0x989680;\n\t"
        "@!P bra W%=;\n\t"
        "}"
        :: "r"(mbar), "r"(parity) : "memory");
}

// Dual-path hybrid: R11's bulk-copy ring (async engine) streams ~half the
// rows; the other half flows through direct LDG (LSU path) with a
// 1-iteration register prefetch interleaved in the same loop. Tests whether
// the two memory paths' ~4.6/4.9 TB/s ceilings are independent and additive.
__global__ __launch_bounds__(NTHR, 4) void fused_loss_kernel(
    const float* __restrict__ x,
    const int* __restrict__ pol,      // int32 (JAX x64-disabled downcasts int64)
    const float* __restrict__ s,
    float* __restrict__ out)
{
    __shared__ float4 ring[STAGES][D4];              // 32 KB static
    __shared__ alignas(8) unsigned long long mbar[STAGES];

    const float4* __restrict__ x4 = (const float4*)x;
    const float4* __restrict__ s4 = (const float4*)s;
    const int tid = threadIdx.x;
    const int bid = blockIdx.x;

    // contiguous row range for this CTA (27 or 28 rows)
    const int r0 = (int)(((long long)bid * B_ROWS) / NBLK);
    const int r1 = (int)(((long long)(bid + 1) * B_ROWS) / NBLK);
    const int nrows = r1 - r0;
    const int ndir  = nrows / 2;                     // direct-LDG rows (13/14)
    const int nring = nrows - ndir;                  // ring rows (14)
    const int d0    = r0 + nring;                    // first direct row

    const uint32_t ring_base = smem_u32(&ring[0][0]);
    const uint32_t mbar_base = smem_u32(&mbar[0]);

    if (tid == 0) {
#pragma unroll
        for (int st = 0; st < STAGES; st++) mbar_init(mbar_base + 8 * st, 1);
        asm volatile("fence.proxy.async.shared::cta;" ::: "memory");
    }
    __syncthreads();

    // prologue: fill the ring (async engine path)
    if (tid == 0) {
#pragma unroll
        for (int k = 0; k < STAGES; k++) {
            if (k < nring) {
                uint32_t mb = mbar_base + 8 * k;
                mbar_expect_tx(mb, ROW_BYTES);
                bulk_g2s(ring_base + k * ROW_BYTES,
                         x + (size_t)(r0 + k) * D_DIM, ROW_BYTES, mb);
            }
        }
    }

    float a0 = 0.f, a1 = 0.f, a2 = 0.f, a3 = 0.f;

    // prefetch direct row 0 (LSU path, evict-first)
    float4 pxv0, pxv1;
    int pp = 0;
    if (ndir > 0) {
        const float4* xd = x4 + (size_t)d0 * D4;
        pxv0 = __ldcs(&xd[tid]);
        pxv1 = __ldcs(&xd[tid + NTHR]);
        pp   = __ldg(&pol[d0]);
    }

    int st = 0, ph = 0;
    for (int k = 0; k < nring; k++) {
        mbar_wait(mbar_base + 8 * st, (uint32_t)ph);

        // ---- ring row (R11's proven consume) ----
        {
            int p = __ldg(&pol[r0 + k]);
            p = min(max(p, 0), 2);
            const float4* sp = s4 + p * D4;
            const float4* xr = ring[st];
            float4 xv0 = xr[tid];
            float4 xv1 = xr[tid + NTHR];
            float4 sv0 = __ldg(&sp[tid]);
            float4 sv1 = __ldg(&sp[tid + NTHR]);
            float d0f = xv0.x - sv0.x, d1f = xv0.y - sv0.y;
            float d2f = xv0.z - sv0.z, d3f = xv0.w - sv0.w;
            a0 += d0f * d0f;  a1 += d1f * d1f;
            a2 += d2f * d2f;  a3 += d3f * d3f;
            d0f = xv1.x - sv1.x; d1f = xv1.y - sv1.y;
            d2f = xv1.z - sv1.z; d3f = xv1.w - sv1.w;
            a0 += d0f * d0f;  a1 += d1f * d1f;
            a2 += d2f * d2f;  a3 += d3f * d3f;
        }
        __syncthreads();                             // stage st fully consumed

        if (tid == 0 && k + STAGES < nring) {
            uint32_t mb = mbar_base + 8 * st;
            mbar_expect_tx(mb, ROW_BYTES);
            bulk_g2s(ring_base + st * ROW_BYTES,
                     x + (size_t)(r0 + k + STAGES) * D_DIM, ROW_BYTES, mb);
        }

        // ---- direct row (consume prefetched, then prefetch next) ----
        if (k < ndir) {
            int p2 = min(max(pp, 0), 2);
            const float4* sp2 = s4 + p2 * D4;
            float4 sv0 = __ldg(&sp2[tid]);
            float4 sv1 = __ldg(&sp2[tid + NTHR]);
            float d0f = pxv0.x - sv0.x, d1f = pxv0.y - sv0.y;
            float d2f = pxv0.z - sv0.z, d3f = pxv0.w - sv0.w;
            a0 += d0f * d0f;  a1 += d1f * d1f;
            a2 += d2f * d2f;  a3 += d3f * d3f;
            d0f = pxv1.x - sv1.x; d1f = pxv1.y - sv1.y;
            d2f = pxv1.z - sv1.z; d3f = pxv1.w - sv1.w;
            a0 += d0f * d0f;  a1 += d1f * d1f;
            a2 += d2f * d2f;  a3 += d3f * d3f;

            if (k + 1 < ndir) {                      // issue next; consumed next iter
                const float4* xn = x4 + (size_t)(d0 + k + 1) * D4;
                pxv0 = __ldcs(&xn[tid]);
                pxv1 = __ldcs(&xn[tid + NTHR]);
                pp   = __ldg(&pol[d0 + k + 1]);
            }
        }
        if (++st == STAGES) { st = 0; ph ^= 1; }
    }
    float acc = (a0 + a1) + (a2 + a3);

    // ---- block reduce ----
    const int wid  = tid >> 5;
    const int lane = tid & 31;
#pragma unroll
    for (int off = 16; off > 0; off >>= 1)
        acc += __shfl_down_sync(0xFFFFFFFFu, acc, off);

    __shared__ float wsum[WARPS_PER_BLK];
    if (lane == 0) wsum[wid] = acc;
    __syncthreads();

    __shared__ unsigned int s_islast;
    if (tid == 0) {
        float bsum = 0.f;
#pragma unroll
        for (int w = 0; w < WARPS_PER_BLK; w++) bsum += wsum[w];
        g_partials[bid] = bsum;
        __threadfence();
        unsigned int prev = atomicAdd(&g_count, 1u);
        s_islast = (prev == NBLK - 1) ? 1u : 0u;
    }
    __syncthreads();
    if (!s_islast) return;

    // ---- last block: fold partials + cos^2 terms ----
    float racc = 0.0f;
    for (int j = tid; j < NBLK; j += NTHR) racc += g_partials[j];

    // cos_(a,b) = dot(a,b) / sqrt(||a||^2) * sqrt(||b||^2) (reference precedence)
    // => cos_^2 = dot^2 * ||b||^2 / ||a||^2
    float n0 = 0.f, n1 = 0.f, n2 = 0.f, d01 = 0.f, d02 = 0.f, d12 = 0.f;
    for (int j = tid; j < D_DIM; j += NTHR) {
        float a = s[j];
        float b = s[D_DIM + j];
        float c = s[2 * D_DIM + j];
        n0  += a * a;  n1  += b * b;  n2  += c * c;
        d01 += a * b;  d02 += a * c;  d12 += b * c;
    }

    __shared__ float rm[7][NTHR];
    rm[0][tid] = racc;
    rm[1][tid] = n0;  rm[2][tid] = n1;  rm[3][tid] = n2;
    rm[4][tid] = d01; rm[5][tid] = d02; rm[6][tid] = d12;
    __syncthreads();
#pragma unroll
    for (int q = NTHR / 2; q > 0; q >>= 1) {
        if (tid < q) {
#pragma unroll
            for (int m = 0; m < 7; m++) rm[m][tid] += rm[m][tid + q];
        }
        __syncthreads();
    }

    if (tid == 0) {
        float L   = rm[0][0];
        float N0  = rm[1][0], N1 = rm[2][0], N2 = rm[3][0];
        float D01 = rm[4][0], D02 = rm[5][0], D12 = rm[6][0];
        float c01 = D01 * D01 * (N1 / N0);
        float c02 = D02 * D02 * (N2 / N0);
        float c12 = D12 * D12 * (N2 / N1);
        out[0] = L + c01 + c02 + c12;
        g_count = 0;                 // reset for next graph replay
    }
}

extern "C" void kernel_launch(void* const* d_in, const int* in_sizes, int n_in,
                              void* d_out, int out_size)
{
    const float* x   = (const float*)d_in[0];   // inputs [16384, 2048] f32
    const int*   pol = (const int*)d_in[1];     // polarity [16384] int32
    const float* s   = (const float*)d_in[2];   // standar_score [3, 2048] f32
    float* out = (float*)d_out;

    fused_loss_kernel<<<NBLK, NTHR>>>(x, pol, s, out);
}

// round 17
// speedup vs baseline: 1.2686x; 1.2686x over previous
#include <cuda_runtime.h>
#include <cstdint>

// Problem shape (fixed by the dataset)
#define B_ROWS   16384
#define D_DIM    2048
#define D4       512                  // float4 per row (8 KB)
#define ROW_BYTES 8192
#define NBLK     592                  // 148 SMs x 4 CTAs, persistent, one wave
#define NTHR     256
#define STAGES   4                    // 4-deep bulk-copy ring, 8 KB/stage
#define WARPS_PER_BLK (NTHR / 32)

__device__ float g_partials[NBLK];
__device__ unsigned int g_count;      // zero-init at load; reset by last block

__device__ __forceinline__ uint32_t smem_u32(const void* p) {
    return (uint32_t)__cvta_generic_to_shared(p);
}
__device__ __forceinline__ void mbar_init(uint32_t mbar, uint32_t cnt) {
    asm volatile("mbarrier.init.shared.b64 [%0], %1;" :: "r"(mbar), "r"(cnt) : "memory");
}
__device__ __forceinline__ void mbar_expect_tx(uint32_t mbar, uint32_t bytes) {
    asm volatile("mbarrier.arrive.expect_tx.shared.b64 _, [%0], %1;"
                 :: "r"(mbar), "r"(bytes) : "memory");
}
__device__ __forceinline__ void bulk_g2s(uint32_t dst, const void* src,
                                         uint32_t bytes, uint32_t mbar) {
    asm volatile(
        "cp.async.bulk.shared::cluster.global.mbarrier::complete_tx::bytes "
        "[%0], [%1], %2, [%3];"
        :: "r"(dst), "l"(src), "r"(bytes), "r"(mbar) : "memory");
}
__device__ __forceinline__ void mbar_wait(uint32_t mbar, uint32_t parity) {
    asm volatile(
        "{\n\t"
        ".reg .pred P;\n\t"
        "W%=:\n\t"
        "mbarrier.try_wait.parity.acquire.cta.shared::cta.b64 P, [%0], %1;\n\t"
        "@!P bra W%=;\n\t"
        "}"
        :: "r"(mbar), "r"(parity) : "memory");
}

// CONVERGED KERNEL (= R11, best measured: 28.5us kernel / 4.85 TB/s).
// Persistent CTAs; x rows delivered by cp.async.bulk (async-copy engine ->
// smem, mbarrier tx-completion): zero per-element SM issue for the stream.
// 10 structural variants tested (R4-R16); every deviation from this shape
// regressed. ~4.85 TB/s is the effective chip ceiling for this pattern.
__global__ __launch_bounds__(NTHR) void fused_loss_kernel(
    const float* __restrict__ x,
    const int* __restrict__ pol,      // int32 (JAX x64-disabled downcasts int64)
    const float* __restrict__ s,
    float* __restrict__ out)
{
    __shared__ float4 ring[STAGES][D4];                 // 32 KB
    __shared__ alignas(8) unsigned long long mbar[STAGES];

    const float4* __restrict__ s4 = (const float4*)s;
    const int tid = threadIdx.x;
    const int bid = blockIdx.x;

    // contiguous row chunk for this CTA: [r0, r1), 27 or 28 rows
    const int r0 = (bid * B_ROWS) / NBLK;
    const int r1 = ((bid + 1) * B_ROWS) / NBLK;
    const int nrows = r1 - r0;

    const uint32_t ring_base = smem_u32(&ring[0][0]);
    const uint32_t mbar_base = smem_u32(&mbar[0]);

    if (tid == 0) {
#pragma unroll
        for (int st = 0; st < STAGES; st++) mbar_init(mbar_base + 8 * st, 1);
        asm volatile("fence.proxy.async.shared::cta;" ::: "memory");
    }
    __syncthreads();

    // prologue: fill the ring
    if (tid == 0) {
#pragma unroll
        for (int st = 0; st < STAGES; st++) {
            if (st < nrows) {
                uint32_t mb = mbar_base + 8 * st;
                mbar_expect_tx(mb, ROW_BYTES);
                bulk_g2s(ring_base + st * ROW_BYTES,
                         x + (size_t)(r0 + st) * D_DIM, ROW_BYTES, mb);
            }
        }
    }

    float a0 = 0.f, a1 = 0.f, a2 = 0.f, a3 = 0.f;

    for (int k = 0; k < nrows; k++) {
        const int st = k & (STAGES - 1);
        const uint32_t ph = (uint32_t)((k >> 2) & 1);
        mbar_wait(mbar_base + 8 * st, ph);              // acquire: smem data ready

        int p = __ldg(&pol[r0 + k]);
        p = min(max(p, 0), 2);                          // keep gather in-bounds
        const float4* sp = s4 + p * D4;
        const float4* xr = ring[st];

        {
            // thread covers f = tid and tid+256 (conflict-free LDS.128)
            float4 xv0 = xr[tid];
            float4 xv1 = xr[tid + NTHR];
            float4 sv0 = __ldg(&sp[tid]);
            float4 sv1 = __ldg(&sp[tid + NTHR]);
            float d0, d1, d2, d3;
            d0 = xv0.x - sv0.x; d1 = xv0.y - sv0.y;
            d2 = xv0.z - sv0.z; d3 = xv0.w - sv0.w;
            a0 += d0 * d0;  a1 += d1 * d1;
            a2 += d2 * d2;  a3 += d3 * d3;
            d0 = xv1.x - sv1.x; d1 = xv1.y - sv1.y;
            d2 = xv1.z - sv1.z; d3 = xv1.w - sv1.w;
            a0 += d0 * d0;  a1 += d1 * d1;
            a2 += d2 * d2;  a3 += d3 * d3;
        }
        __syncthreads();                                // slot st fully consumed

        const int kn = k + STAGES;
        if (tid == 0 && kn < nrows) {
            uint32_t mb = mbar_base + 8 * st;
            mbar_expect_tx(mb, ROW_BYTES);
            bulk_g2s(ring_base + st * ROW_BYTES,
                     x + (size_t)(r0 + kn) * D_DIM, ROW_BYTES, mb);
        }
    }
    float acc = (a0 + a1) + (a2 + a3);

    // ---- block reduce ----
    const int wid  = tid >> 5;
    const int lane = tid & 31;
#pragma unroll
    for (int off = 16; off > 0; off >>= 1)
        acc += __shfl_down_sync(0xFFFFFFFFu, acc, off);

    __shared__ float wsum[WARPS_PER_BLK];
    if (lane == 0) wsum[wid] = acc;
    __syncthreads();

    __shared__ unsigned int s_islast;
    if (tid == 0) {
        float bsum = 0.f;
#pragma unroll
        for (int w = 0; w < WARPS_PER_BLK; w++) bsum += wsum[w];
        g_partials[bid] = bsum;
        __threadfence();
        unsigned int prev = atomicAdd(&g_count, 1u);
        s_islast = (prev == NBLK - 1) ? 1u : 0u;
    }
    __syncthreads();
    if (!s_islast) return;

    // ---- last block: fold partials + cos^2 terms ----
    float racc = 0.0f;
    for (int j = tid; j < NBLK; j += NTHR) racc += g_partials[j];

    // cos_(a,b) = dot(a,b) / sqrt(||a||^2) * sqrt(||b||^2) (reference precedence)
    // => cos_^2 = dot^2 * ||b||^2 / ||a||^2
    float n0 = 0.f, n1 = 0.f, n2 = 0.f, d01 = 0.f, d02 = 0.f, d12 = 0.f;
    for (int j = tid; j < D_DIM; j += NTHR) {
        float a = s[j];
        float b = s[D_DIM + j];
        float c = s[2 * D_DIM + j];
        n0  += a * a;  n1  += b * b;  n2  += c * c;
        d01 += a * b;  d02 += a * c;  d12 += b * c;
    }

    __shared__ float rm[7][NTHR];
    rm[0][tid] = racc;
    rm[1][tid] = n0;  rm[2][tid] = n1;  rm[3][tid] = n2;
    rm[4][tid] = d01; rm[5][tid] = d02; rm[6][tid] = d12;
    __syncthreads();
#pragma unroll
    for (int st = NTHR / 2; st > 0; st >>= 1) {
        if (tid < st) {
#pragma unroll
            for (int q = 0; q < 7; q++) rm[q][tid] += rm[q][tid + st];
        }
        __syncthreads();
    }

    if (tid == 0) {
        float L   = rm[0][0];
        float N0  = rm[1][0], N1 = rm[2][0], N2 = rm[3][0];
        float D01 = rm[4][0], D02 = rm[5][0], D12 = rm[6][0];
        float c01 = D01 * D01 * (N1 / N0);
        float c02 = D02 * D02 * (N2 / N0);
        float c12 = D12 * D12 * (N2 / N1);
        out[0] = L + c01 + c02 + c12;
        g_count = 0;                 // reset for next graph replay
    }
}

extern "C" void kernel_launch(void* const* d_in, const int* in_sizes, int n_in,
                              void* d_out, int out_size)
{
    const float* x   = (const float*)d_in[0];   // inputs [16384, 2048] f32
    const int*   pol = (const int*)d_in[1];     // polarity [16384] int32
    const float* s   = (const float*)d_in[2];   // standar_score [3, 2048] f32
    float* out = (float*)d_out;

    fused_loss_kernel<<<NBLK, NTHR>>>(x, pol, s, out);
}